// round 6
// baseline (speedup 1.0000x reference)
#include <cuda_runtime.h>
#include <cuda_bf16.h>
#include <cstdint>

// out[b,p,o] = relu(sum_k x[b,p,k] * W[p,k,o] + bias[p,o])
// B=16384, P=K=O=64 fp32.
// CTA = 128 b-rows x one part p, 8 warps, warp tile M=32,N=32
// (warps 0-3: cols 0-31, warps 4-7: cols 32-63).
// Split-bf16 (hi+lo), 3 MMA terms, fp32 accum, mma.sync.m16n8k16.
// sigma: k-permutation (A loads are LDG.128 in fragment layout)
// tau:   n-permutation (C stores are STG.128, 4 contiguous cols/thread)

#define PP 64
#define KK 64
#define OO 64
#define BLOCK_B 128
#define THREADS 256

#define ASTRIDE 72                         // bf16 elems per smem row (144 B)
#define ROWB (ASTRIDE * 2)                 // 144 bytes per smem row
#define SW_BYTES (KK * ROWB)               // 9216
#define SM_WHI 0
#define SM_WLO (SM_WHI + SW_BYTES)
#define SM_TOTAL (SM_WLO + SW_BYTES)       // 18432

__device__ __forceinline__ uint32_t smem_u32(const void* p) {
    uint32_t a;
    asm("{ .reg .u64 t; cvta.to.shared.u64 t, %1; cvt.u32.u64 %0, t; }" : "=r"(a) : "l"(p));
    return a;
}

// pack word: lo16 = bf16(a), hi16 = bf16(b)
__device__ __forceinline__ uint32_t pack_bf16(float a, float b) {
    uint32_t r;
    asm("cvt.rn.bf16x2.f32 %0, %1, %2;" : "=r"(r) : "f"(b), "f"(a));
    return r;
}
__device__ __forceinline__ float bf_lo(uint32_t h) { return __uint_as_float(h << 16); }
__device__ __forceinline__ float bf_hi(uint32_t h) { return __uint_as_float(h & 0xFFFF0000u); }

#define LDSM_X4_T(r0, r1, r2, r3, addr) \
    asm volatile("ldmatrix.sync.aligned.m8n8.x4.trans.shared.b16 {%0,%1,%2,%3}, [%4];" \
                 : "=r"(r0), "=r"(r1), "=r"(r2), "=r"(r3) : "r"(addr))

#define MMA_BF16(d, a, b0_, b1_) \
    asm volatile("mma.sync.aligned.m16n8k16.row.col.f32.bf16.bf16.f32 " \
                 "{%0,%1,%2,%3}, {%4,%5,%6,%7}, {%8,%9}, {%0,%1,%2,%3};" \
                 : "+f"((d)[0]), "+f"((d)[1]), "+f"((d)[2]), "+f"((d)[3]) \
                 : "r"((a)[0]), "r"((a)[1]), "r"((a)[2]), "r"((a)[3]), \
                   "r"(b0_), "r"(b1_))

extern "C" __global__ void __launch_bounds__(THREADS, 3)
parts_hmma_occ_kernel(const float* __restrict__ x,
                      const float* __restrict__ W,
                      const float* __restrict__ bias,
                      float* __restrict__ out)
{
    extern __shared__ char smem[];
    const uint32_t sb = smem_u32(smem);
    const int t     = threadIdx.x;
    const int wid   = t >> 5;
    const int lane  = t & 31;
    const int mwid  = wid & 3;           // M group: rows mwid*32..+31
    const int nhalf = wid >> 2;          // N half: cols nhalf*32..+31
    const int p     = blockIdx.y;
    const int b0    = blockIdx.x * BLOCK_B;

    const int w32  = mwid * 32;
    const int qrow = lane >> 2;          // 0..7
    const int q4   = (lane & 3) * 4;     // phys-k / out-col quad offset

    const size_t RS = (size_t)(PP * KK); // 4096 floats, batch row stride

    // Per-thread A base: phys k cols q4..q4+3 of each 16-k chunk.
    const float* xq = x + (size_t)(b0 + w32 + qrow) * RS + p * KK + q4;

    // ---- Prefetch A chunk ks=0: [mi][rowsel] ----
    float4 xf[2][2];
    #pragma unroll
    for (int mi = 0; mi < 2; mi++)
        #pragma unroll
        for (int rs = 0; rs < 2; rs++)
            xf[mi][rs] = *(const float4*)(xq + (mi * 16 + rs * 8) * RS);

    // ---- W[p] -> smem with sigma (rows) and tau (cols) permutations ----
    // sigma: phys k -> smem row sr = (k&~15) + 2*((k>>2)&3) + (k&1) + 8*((k>>1)&1)
    // tau:   phys o (=c4*4+j) -> smem col (2*(c4>>2)+(j>>1))*8 + 2*(c4&3) + (j&1)
    #pragma unroll
    for (int i = 0; i < 4; i++) {
        int idx4 = i * 256 + t;
        int k    = idx4 >> 4;
        int c4   = idx4 & 15;
        float4 v = *(const float4*)(W + p * (KK * OO) + k * OO + c4 * 4);
        uint32_t h0 = pack_bf16(v.x, v.y);
        uint32_t h1 = pack_bf16(v.z, v.w);
        uint32_t l0 = pack_bf16(v.x - bf_lo(h0), v.y - bf_hi(h0));
        uint32_t l1 = pack_bf16(v.z - bf_lo(h1), v.w - bf_hi(h1));
        int w  = k & 15;
        int sr = (k & ~15) + 2 * (w >> 2) + (w & 1) + 8 * ((w >> 1) & 1);
        int col0 = (2 * (c4 >> 2)) * 8 + 2 * (c4 & 3);   // bf16 units, pair j=0,1
        int col1 = col0 + 8;                              // pair j=2,3
        uint32_t base = (uint32_t)(sr * ROWB);
        *(uint32_t*)(smem + SM_WHI + base + col0 * 2) = h0;
        *(uint32_t*)(smem + SM_WHI + base + col1 * 2) = h1;
        *(uint32_t*)(smem + SM_WLO + base + col0 * 2) = l0;
        *(uint32_t*)(smem + SM_WLO + base + col1 * 2) = l1;
    }
    __syncthreads();

    // ---- Mainloop ----
    const int lrow  = lane & 15;
    const int lcol8 = (lane >> 4) * 8;

    float acc[2][4][4];
    #pragma unroll
    for (int mi = 0; mi < 2; mi++)
        #pragma unroll
        for (int ni = 0; ni < 4; ni++)
            #pragma unroll
            for (int r = 0; r < 4; r++)
                acc[mi][ni][r] = 0.0f;

    #pragma unroll
    for (int ks = 0; ks < 4; ks++) {
        const int k0 = ks * 16;

        // Convert current A chunk to hi/lo fragments.
        // a0 <- (rs0).xy, a1 <- (rs1).xy, a2 <- (rs0).zw, a3 <- (rs1).zw
        uint32_t ah[2][4], al[2][4];
        #pragma unroll
        for (int mi = 0; mi < 2; mi++) {
            float4 v0 = xf[mi][0];
            float4 v1 = xf[mi][1];
            uint32_t h;
            h = pack_bf16(v0.x, v0.y); ah[mi][0] = h;
            al[mi][0] = pack_bf16(v0.x - bf_lo(h), v0.y - bf_hi(h));
            h = pack_bf16(v1.x, v1.y); ah[mi][1] = h;
            al[mi][1] = pack_bf16(v1.x - bf_lo(h), v1.y - bf_hi(h));
            h = pack_bf16(v0.z, v0.w); ah[mi][2] = h;
            al[mi][2] = pack_bf16(v0.z - bf_lo(h), v0.w - bf_hi(h));
            h = pack_bf16(v1.z, v1.w); ah[mi][3] = h;
            al[mi][3] = pack_bf16(v1.z - bf_lo(h), v1.w - bf_hi(h));
        }

        // Prefetch next chunk
        if (ks < 3) {
            #pragma unroll
            for (int mi = 0; mi < 2; mi++)
                #pragma unroll
                for (int rs = 0; rs < 2; rs++)
                    xf[mi][rs] = *(const float4*)(xq + (mi * 16 + rs * 8) * RS
                                                     + (ks + 1) * 16);
        }

        #pragma unroll
        for (int ng = 0; ng < 2; ng++) {
            uint32_t bh[4], bl[4];
            uint32_t off = (uint32_t)((k0 + lrow) * ROWB
                                      + (nhalf * 32 + ng * 16 + lcol8) * 2);
            LDSM_X4_T(bh[0], bh[1], bh[2], bh[3], sb + SM_WHI + off);
            LDSM_X4_T(bl[0], bl[1], bl[2], bl[3], sb + SM_WLO + off);

            #pragma unroll
            for (int mi = 0; mi < 2; mi++) {
                MMA_BF16(acc[mi][2 * ng + 0], ah[mi], bh[0], bh[1]);
                MMA_BF16(acc[mi][2 * ng + 1], ah[mi], bh[2], bh[3]);
                MMA_BF16(acc[mi][2 * ng + 0], ah[mi], bl[0], bl[1]);
                MMA_BF16(acc[mi][2 * ng + 1], ah[mi], bl[2], bl[3]);
                MMA_BF16(acc[mi][2 * ng + 0], al[mi], bh[0], bh[1]);
                MMA_BF16(acc[mi][2 * ng + 1], al[mi], bh[2], bh[3]);
            }
        }
    }

    // ---- Epilogue (tau): thread owns out cols (nhalf*2+g)*16 + q4 .. +3 ----
    float4 bv[2];
    #pragma unroll
    for (int g = 0; g < 2; g++)
        bv[g] = *(const float4*)(bias + p * OO + (nhalf * 2 + g) * 16 + q4);

    #pragma unroll
    for (int mi = 0; mi < 2; mi++) {
        #pragma unroll
        for (int rs = 0; rs < 2; rs++) {
            const int row = b0 + w32 + mi * 16 + rs * 8 + qrow;
            float* op = out + (size_t)row * RS + p * OO + q4;
            #pragma unroll
            for (int g = 0; g < 2; g++) {
                float4 v;
                v.x = fmaxf(acc[mi][2 * g + 0][rs * 2 + 0] + bv[g].x, 0.0f);
                v.y = fmaxf(acc[mi][2 * g + 0][rs * 2 + 1] + bv[g].y, 0.0f);
                v.z = fmaxf(acc[mi][2 * g + 1][rs * 2 + 0] + bv[g].z, 0.0f);
                v.w = fmaxf(acc[mi][2 * g + 1][rs * 2 + 1] + bv[g].w, 0.0f);
                *(float4*)(op + (nhalf * 2 + g) * 16) = v;
            }
        }
    }
}

extern "C" void kernel_launch(void* const* d_in, const int* in_sizes, int n_in,
                              void* d_out, int out_size)
{
    const float* x    = (const float*)d_in[0];
    const float* W    = (const float*)d_in[1];
    const float* bias = (const float*)d_in[2];
    float* out = (float*)d_out;

    const int B = in_sizes[0] / (PP * KK);   // 16384

    cudaFuncSetAttribute(parts_hmma_occ_kernel,
                         cudaFuncAttributeMaxDynamicSharedMemorySize, SM_TOTAL);

    dim3 grid(B / BLOCK_B, PP);
    parts_hmma_occ_kernel<<<grid, THREADS, SM_TOTAL>>>(x, W, bias, out);
}

// round 7
// speedup vs baseline: 1.1399x; 1.1399x over previous
#include <cuda_runtime.h>
#include <cuda_bf16.h>
#include <cstdint>

// out[b,p,o] = relu(sum_k x[b,p,k] * W[p,k,o] + bias[p,o])
// B=16384, P=K=O=64 fp32.
// CTA = 256 b-rows x one part p, 8 warps, warp tile M=32,N=64 (R5 shape).
// Split-bf16 (hi+lo), 3 MMA terms, fp32 accum, mma.sync.m16n8k16.
// sigma: k-permutation (A loads are LDG.128 in fragment layout)
// tau:   n-permutation (C stores are STG.128, 4 contiguous cols/thread)
// Streaming hints: __ldcs for x, __stcs for out (single-touch data).

#define PP 64
#define KK 64
#define OO 64
#define BLOCK_B 256
#define THREADS 256

#define ASTRIDE 72                         // bf16 elems per smem row (144 B)
#define ROWB (ASTRIDE * 2)                 // 144 bytes per smem row
#define SW_BYTES (KK * ROWB)               // 9216
#define SM_WHI 0
#define SM_WLO (SM_WHI + SW_BYTES)
#define SM_TOTAL (SM_WLO + SW_BYTES)       // 18432

__device__ __forceinline__ uint32_t smem_u32(const void* p) {
    uint32_t a;
    asm("{ .reg .u64 t; cvta.to.shared.u64 t, %1; cvt.u32.u64 %0, t; }" : "=r"(a) : "l"(p));
    return a;
}

// pack word: lo16 = bf16(a), hi16 = bf16(b)
__device__ __forceinline__ uint32_t pack_bf16(float a, float b) {
    uint32_t r;
    asm("cvt.rn.bf16x2.f32 %0, %1, %2;" : "=r"(r) : "f"(b), "f"(a));
    return r;
}
__device__ __forceinline__ float bf_lo(uint32_t h) { return __uint_as_float(h << 16); }
__device__ __forceinline__ float bf_hi(uint32_t h) { return __uint_as_float(h & 0xFFFF0000u); }

#define LDSM_X4_T(r0, r1, r2, r3, addr) \
    asm volatile("ldmatrix.sync.aligned.m8n8.x4.trans.shared.b16 {%0,%1,%2,%3}, [%4];" \
                 : "=r"(r0), "=r"(r1), "=r"(r2), "=r"(r3) : "r"(addr))

#define MMA_BF16(d, a, b0_, b1_) \
    asm volatile("mma.sync.aligned.m16n8k16.row.col.f32.bf16.bf16.f32 " \
                 "{%0,%1,%2,%3}, {%4,%5,%6,%7}, {%8,%9}, {%0,%1,%2,%3};" \
                 : "+f"((d)[0]), "+f"((d)[1]), "+f"((d)[2]), "+f"((d)[3]) \
                 : "r"((a)[0]), "r"((a)[1]), "r"((a)[2]), "r"((a)[3]), \
                   "r"(b0_), "r"(b1_))

extern "C" __global__ void __launch_bounds__(THREADS, 2)
parts_hmma_big_kernel(const float* __restrict__ x,
                      const float* __restrict__ W,
                      const float* __restrict__ bias,
                      float* __restrict__ out)
{
    extern __shared__ char smem[];
    const uint32_t sb = smem_u32(smem);
    const int t    = threadIdx.x;
    const int wid  = t >> 5;             // 0..7, warp owns rows wid*32..+31
    const int lane = t & 31;
    const int p    = blockIdx.y;
    const int b0   = blockIdx.x * BLOCK_B;

    const int w32  = wid * 32;
    const int qrow = lane >> 2;          // 0..7
    const int q4   = (lane & 3) * 4;     // phys-k / out-col quad offset

    const size_t RS = (size_t)(PP * KK); // 4096 floats, batch row stride

    // Per-thread A base: phys cols q4..q4+3 of each 16-k chunk.
    const float* xq = x + (size_t)(b0 + w32 + qrow) * RS + p * KK + q4;

    // ---- Prefetch A chunk ks=0: [mi][rowsel] ----
    float4 xf[2][2];
    #pragma unroll
    for (int mi = 0; mi < 2; mi++)
        #pragma unroll
        for (int rs = 0; rs < 2; rs++)
            xf[mi][rs] = __ldcs((const float4*)(xq + (mi * 16 + rs * 8) * RS));

    // ---- W[p] -> smem with sigma (rows) and tau (cols) permutations ----
    // sigma: phys k -> smem row sr = (k&~15) + 2*((k>>2)&3) + (k&1) + 8*((k>>1)&1)
    // tau:   phys o (=c4*4+j) -> smem col (2*(c4>>2)+(j>>1))*8 + 2*(c4&3) + (j&1)
    #pragma unroll
    for (int i = 0; i < 4; i++) {
        int idx4 = i * 256 + t;
        int k    = idx4 >> 4;
        int c4   = idx4 & 15;
        float4 v = *(const float4*)(W + p * (KK * OO) + k * OO + c4 * 4);
        uint32_t h0 = pack_bf16(v.x, v.y);
        uint32_t h1 = pack_bf16(v.z, v.w);
        uint32_t l0 = pack_bf16(v.x - bf_lo(h0), v.y - bf_hi(h0));
        uint32_t l1 = pack_bf16(v.z - bf_lo(h1), v.w - bf_hi(h1));
        int w  = k & 15;
        int sr = (k & ~15) + 2 * (w >> 2) + (w & 1) + 8 * ((w >> 1) & 1);
        int col0 = (2 * (c4 >> 2)) * 8 + 2 * (c4 & 3);   // bf16 units, pair j=0,1
        int col1 = col0 + 8;                              // pair j=2,3
        uint32_t base = (uint32_t)(sr * ROWB);
        *(uint32_t*)(smem + SM_WHI + base + col0 * 2) = h0;
        *(uint32_t*)(smem + SM_WHI + base + col1 * 2) = h1;
        *(uint32_t*)(smem + SM_WLO + base + col0 * 2) = l0;
        *(uint32_t*)(smem + SM_WLO + base + col1 * 2) = l1;
    }
    __syncthreads();

    // ---- Mainloop ----
    const int lrow  = lane & 15;
    const int lcol8 = (lane >> 4) * 8;

    float acc[2][8][4];
    #pragma unroll
    for (int mi = 0; mi < 2; mi++)
        #pragma unroll
        for (int ni = 0; ni < 8; ni++)
            #pragma unroll
            for (int r = 0; r < 4; r++)
                acc[mi][ni][r] = 0.0f;

    #pragma unroll
    for (int ks = 0; ks < 4; ks++) {
        const int k0 = ks * 16;

        // Convert current A chunk to hi/lo fragments.
        // a0 <- (rs0).xy, a1 <- (rs1).xy, a2 <- (rs0).zw, a3 <- (rs1).zw
        uint32_t ah[2][4], al[2][4];
        #pragma unroll
        for (int mi = 0; mi < 2; mi++) {
            float4 v0 = xf[mi][0];
            float4 v1 = xf[mi][1];
            uint32_t h;
            h = pack_bf16(v0.x, v0.y); ah[mi][0] = h;
            al[mi][0] = pack_bf16(v0.x - bf_lo(h), v0.y - bf_hi(h));
            h = pack_bf16(v1.x, v1.y); ah[mi][1] = h;
            al[mi][1] = pack_bf16(v1.x - bf_lo(h), v1.y - bf_hi(h));
            h = pack_bf16(v0.z, v0.w); ah[mi][2] = h;
            al[mi][2] = pack_bf16(v0.z - bf_lo(h), v0.w - bf_hi(h));
            h = pack_bf16(v1.z, v1.w); ah[mi][3] = h;
            al[mi][3] = pack_bf16(v1.z - bf_lo(h), v1.w - bf_hi(h));
        }

        // Prefetch next chunk
        if (ks < 3) {
            #pragma unroll
            for (int mi = 0; mi < 2; mi++)
                #pragma unroll
                for (int rs = 0; rs < 2; rs++)
                    xf[mi][rs] = __ldcs((const float4*)(xq + (mi * 16 + rs * 8) * RS
                                                           + (ks + 1) * 16));
        }

        #pragma unroll
        for (int ng = 0; ng < 4; ng++) {
            uint32_t bh[4], bl[4];
            uint32_t off = (uint32_t)((k0 + lrow) * ROWB + (ng * 16 + lcol8) * 2);
            LDSM_X4_T(bh[0], bh[1], bh[2], bh[3], sb + SM_WHI + off);
            LDSM_X4_T(bl[0], bl[1], bl[2], bl[3], sb + SM_WLO + off);

            #pragma unroll
            for (int mi = 0; mi < 2; mi++) {
                MMA_BF16(acc[mi][2 * ng + 0], ah[mi], bh[0], bh[1]);
                MMA_BF16(acc[mi][2 * ng + 1], ah[mi], bh[2], bh[3]);
                MMA_BF16(acc[mi][2 * ng + 0], ah[mi], bl[0], bl[1]);
                MMA_BF16(acc[mi][2 * ng + 1], ah[mi], bl[2], bl[3]);
                MMA_BF16(acc[mi][2 * ng + 0], al[mi], bh[0], bh[1]);
                MMA_BF16(acc[mi][2 * ng + 1], al[mi], bh[2], bh[3]);
            }
        }
    }

    // ---- Epilogue (tau): thread owns out cols g*16 + q4 .. +3 ----
    float4 bv[4];
    #pragma unroll
    for (int g = 0; g < 4; g++)
        bv[g] = *(const float4*)(bias + p * OO + g * 16 + q4);

    #pragma unroll
    for (int mi = 0; mi < 2; mi++) {
        #pragma unroll
        for (int rs = 0; rs < 2; rs++) {
            const int row = b0 + w32 + mi * 16 + rs * 8 + qrow;
            float* op = out + (size_t)row * RS + p * OO + q4;
            #pragma unroll
            for (int g = 0; g < 4; g++) {
                float4 v;
                v.x = fmaxf(acc[mi][2 * g + 0][rs * 2 + 0] + bv[g].x, 0.0f);
                v.y = fmaxf(acc[mi][2 * g + 0][rs * 2 + 1] + bv[g].y, 0.0f);
                v.z = fmaxf(acc[mi][2 * g + 1][rs * 2 + 0] + bv[g].z, 0.0f);
                v.w = fmaxf(acc[mi][2 * g + 1][rs * 2 + 1] + bv[g].w, 0.0f);
                __stcs((float4*)(op + g * 16), v);
            }
        }
    }
}

extern "C" void kernel_launch(void* const* d_in, const int* in_sizes, int n_in,
                              void* d_out, int out_size)
{
    const float* x    = (const float*)d_in[0];
    const float* W    = (const float*)d_in[1];
    const float* bias = (const float*)d_in[2];
    float* out = (float*)d_out;

    const int B = in_sizes[0] / (PP * KK);   // 16384

    cudaFuncSetAttribute(parts_hmma_big_kernel,
                         cudaFuncAttributeMaxDynamicSharedMemorySize, SM_TOTAL);

    dim3 grid(B / BLOCK_B, PP);
    parts_hmma_big_kernel<<<grid, THREADS, SM_TOTAL>>>(x, W, bias, out);
}